// round 15
// baseline (speedup 1.0000x reference)
#include <cuda_runtime.h>
#include <cuda_fp16.h>
#include <cstdint>

#define BB 32
#define IC 256
#define OC 512
#define HW 56
#define NPIX (HW*HW)
#define NF 64

// scratch (no allocations allowed)
__device__ float g_pp[BB*IC*56];                         // pool partials [b][ic][y]
__device__ int   g_sel[BB*NF];
__device__ __align__(16) unsigned short g_xh[(size_t)BB*56*56*IC]; // NHWC fp16, k-permuted
__device__ __align__(16) unsigned short g_wh[OC*9*IC];   // [oc][tap][ic] fp16, k-permuted

__device__ __forceinline__ uint32_t smem_u32(const void* p){
    uint32_t a;
    asm("{ .reg .u64 t; cvta.to.shared.u64 t, %1; cvt.u32.u64 %0, t; }"
        : "=r"(a) : "l"(p));
    return a;
}
#define CPA(dst, src, szr) \
    asm volatile("cp.async.ca.shared.global [%0], [%1], 16, %2;" \
                 :: "r"(dst), "l"(src), "r"(szr))

// ---------------------------------------------------------------------------
// Kernel 1: prep.  Blocks 0..511: weight transpose+fp16 (k-permuted).
// Blocks 512..2303: x NCHW->NHWC fp16 (k-permuted) + pooling partials.
// Permutation within each 16-ic group: half2 slot d2 (0..7) <- src pair
// (d2&1)*4 + (d2>>1): halves [4t..4t+3] hold ics {2t,2t+1,2t+8,2t+9},
// so each mma thread's (k-lo, k-hi) fragment pair is 8B-contiguous.
// ---------------------------------------------------------------------------
__global__ void prep_kernel(const float* __restrict__ x,
                            const float* __restrict__ w) {
    __shared__ float s[128][57];
    const int tid = threadIdx.x, lane = tid & 31, wp = tid >> 5;

    if (blockIdx.x < 512) {                      // ---- weights ----
        int oc = blockIdx.x;
        float* ws = &s[0][0];                    // 2304 floats
        const float4* src = (const float4*)(w + (size_t)oc*2304);
        for (int i = tid; i < 576; i += 256) ((float4*)ws)[i] = src[i];
        __syncthreads();
        for (int j = tid; j < 1152; j += 256) {  // half2 units
            int tap = j >> 7, h2 = j & 127;
            int d2 = h2 & 7;
            int sp = (h2 & ~7) + (d2 & 1)*4 + (d2 >> 1);
            __half2 h = __floats2half2_rn(ws[(2*sp)*9 + tap],
                                          ws[(2*sp+1)*9 + tap]);
            ((__half2*)g_wh)[(size_t)oc*1152 + j] = h;
        }
        return;
    }
    const int bid = blockIdx.x - 512;
    const int b = bid / 56, y = bid - 56*b;
    const float* xp = x + (size_t)b*IC*NPIX + y*HW;

    for (int p = 0; p < 2; p++) {
        #pragma unroll 4
        for (int i = 0; i < 16; i++) {
            int icl = wp*16 + i;
            int ic  = p*128 + icl;
            const float* row = xp + (size_t)ic*NPIX;
            float v0 = row[lane];
            float v1 = (lane < 24) ? row[lane+32] : 0.f;
            s[icl][lane] = v0;
            if (lane < 24) s[icl][lane+32] = v1;
            float sum = v0 + v1;
            #pragma unroll
            for (int o = 16; o; o >>= 1) sum += __shfl_down_sync(~0u, sum, o);
            if (lane == 0) g_pp[((size_t)b*IC + ic)*56 + y] = sum;
        }
        __syncthreads();
        for (int j = tid; j < 3584; j += 256) {
            int xx = j >> 6, icp = j & 63;
            int d2 = icp & 7;
            int lp = (icp & ~7) + (d2 & 1)*4 + (d2 >> 1);
            __half2 h = __floats2half2_rn(s[2*lp][xx], s[2*lp+1][xx]);
            ((__half2*)g_xh)[((size_t)(b*56+y)*56 + xx)*128 + p*64 + icp] = h;
        }
        __syncthreads();
    }
}

// ---------------------------------------------------------------------------
// Kernel 2: router linear + exact top-64 (tie-break by index, = jax top_k).
// ---------------------------------------------------------------------------
__global__ void router_kernel(const float* __restrict__ rw,
                              const float* __restrict__ rb) {
    int b  = blockIdx.x;
    int oc = threadIdx.x;
    __shared__ float ps[IC];
    __shared__ float rs[OC];
    __shared__ int   cnt;
    if (oc < IC) {
        const float* pp = g_pp + ((size_t)b*IC + oc)*56;
        float sum = 0.f;
        #pragma unroll 8
        for (int y = 0; y < 56; y++) sum += pp[y];
        ps[oc] = sum * (1.0f/NPIX);
    }
    if (oc == 0) cnt = 0;
    __syncthreads();
    float s = rb[oc];
    const float* wrow = rw + (size_t)oc * IC;
    #pragma unroll 8
    for (int i = 0; i < IC; i++) s += ps[i] * wrow[i];
    rs[oc] = s;
    __syncthreads();
    int rank = 0;
    for (int j = 0; j < OC; j++) {
        float v = rs[j];
        rank += (v > s) || (v == s && j < oc);
    }
    if (rank < NF) {
        int pos = atomicAdd(&cnt, 1);
        g_sel[b*NF + pos] = oc;
    }
}

// ---------------------------------------------------------------------------
// Kernel 3: fp16 m16n8k16 implicit-GEMM conv on the 64 selected channels.
// CTA = (b, 8-row slab, 28-col half).  Grid (7, 2, 32), 256 threads, 2/SM.
// Warp = M32 x N64 (one output row).  16 groups of 16 ic.
// 3-stage cp.async ring: wait_group 1 keeps one stage in flight (each stage
// gets 2 compute phases to land); ONE __syncthreads per group — the iter-g
// barrier retires buffer (g-1)%3, exactly the one STAGE(g+2) overwrites.
// k-permuted layout: fragment pairs are single LDS.64, conflict-free.
// ---------------------------------------------------------------------------
#define WSLOT 16
#define WXN   34
#define WINH  (10*WXN*WSLOT)     // 5440 halves
#define BPH   144
#define BH    (64*BPH)           // 9216 halves
#define STGH  (WINH + BH)        // 14656 halves
#define SMEMB (3*STGH*2)         // 87936 bytes

__global__ __launch_bounds__(256, 2)
void conv_mma(const float* __restrict__ bias, float* __restrict__ out)
{
    extern __shared__ unsigned short smh[];
    __shared__ int   s_sel[64];
    __shared__ float s_bias[64];

    const int tid  = threadIdx.x;
    const int w8   = tid >> 5;            // warp id == output row within slab
    const int lane = tid & 31;
    const int g    = lane >> 2;
    const int tq   = lane & 3;
    const int r0   = blockIdx.x * 8;
    const int xoff = blockIdx.y * 28;
    const int b    = blockIdx.z;

    if (tid < 64) {
        int sc = g_sel[b*NF + tid];
        s_sel[tid]  = sc;
        s_bias[tid] = bias[sc];
    }
    __syncthreads();

    float* outb = out + (size_t)b*OC*NPIX;
    const uint32_t base_s = smem_u32(smh);

    // ---- stage one 16-ic group into ring buffer sb ----
    #define STAGE(grp_, sb_) do {                                           \
        uint32_t ws_ = base_s + (sb_)*(STGH*2);                             \
        uint32_t bs_ = ws_ + WINH*2;                                        \
        for (int i = tid; i < 680; i += 256) {                              \
            int ch = i & 1, t = i >> 1;                                     \
            int xw = t % 34, yy = t / 34;                                   \
            int gy = r0 + yy - 1, gx = xoff + xw - 1;                       \
            bool val = ((unsigned)gy < (unsigned)HW) &&                     \
                       ((unsigned)gx < (unsigned)HW);                       \
            const unsigned short* src = val ?                               \
                (g_xh + (((size_t)(b*56+gy)*56+gx)*256 + (grp_)*16 + ch*8)) \
                : g_xh;                                                     \
            CPA(ws_ + (uint32_t)(t*WSLOT + ch*8)*2u, src, val ? 16 : 0);    \
        }                                                                   \
        for (int i = tid; i < 1152; i += 256) {                             \
            int row = i / 18, v = i - row*18;                               \
            int tap = v >> 1, ch = v & 1;                                   \
            const unsigned short* src = g_wh +                              \
                (((size_t)s_sel[row]*9 + tap)*256 + (grp_)*16 + ch*8);      \
            CPA(bs_ + (uint32_t)(row*BPH + tap*16 + ch*8)*2u, src, 16);     \
        }                                                                   \
        asm volatile("cp.async.commit_group;" ::: "memory");                \
    } while(0)

    float acc[2][8][4];
    #pragma unroll
    for (int mt = 0; mt < 2; mt++)
        #pragma unroll
        for (int nt = 0; nt < 8; nt++)
            #pragma unroll
            for (int q = 0; q < 4; q++) acc[mt][nt][q] = 0.f;

    STAGE(0, 0);
    STAGE(1, 1);

    for (int grp = 0; grp < 16; grp++) {
        if (grp < 15)
            asm volatile("cp.async.wait_group 1;" ::: "memory");
        else
            asm volatile("cp.async.wait_group 0;" ::: "memory");
        __syncthreads();
        if (grp + 2 < 16) STAGE(grp + 2, (grp + 2) % 3);

        const unsigned short* win = smh + (grp % 3)*STGH;
        const unsigned short* Bs  = win + WINH;

        #pragma unroll
        for (int tap = 0; tap < 9; tap++) {
            // embedded zero-fill of the 8x28 output patch (all 512 oc)
            {
                int v = (grp*9 + tap)*256 + tid;
                if (v < 28672) {
                    int oc  = v / 56;
                    int rem = v - oc*56;
                    int rr  = rem / 7;
                    int c4  = rem - rr*7;
                    *(float4*)(outb + (size_t)oc*NPIX + (r0+rr)*HW + xoff + c4*4)
                        = make_float4(0.f,0.f,0.f,0.f);
                }
            }
            const int dy = tap/3 - 1;
            const int dx = tap - 3*(tap/3) - 1;

            uint2 bb[8];
            #pragma unroll
            for (int nt = 0; nt < 8; nt++)
                bb[nt] = *(const uint2*)(Bs + (nt*8 + g)*BPH + tap*16 + tq*4);
            #pragma unroll
            for (int mt = 0; mt < 2; mt++) {
                const unsigned short* ap = win +
                    ((w8 + dy + 1)*WXN + mt*16 + g + dx + 1)*WSLOT + tq*4;
                uint2 aLo = *(const uint2*)ap;               // a0 | a2
                uint2 aHi = *(const uint2*)(ap + 8*WSLOT);   // a1 | a3
                #pragma unroll
                for (int nt = 0; nt < 8; nt++) {
                    asm volatile(
                      "mma.sync.aligned.m16n8k16.row.col.f32.f16.f16.f32 "
                      "{%0,%1,%2,%3}, {%4,%5,%6,%7}, {%8,%9}, {%0,%1,%2,%3};"
                      : "+f"(acc[mt][nt][0]), "+f"(acc[mt][nt][1]),
                        "+f"(acc[mt][nt][2]), "+f"(acc[mt][nt][3])
                      : "r"(aLo.x), "r"(aHi.x), "r"(aLo.y), "r"(aHi.y),
                        "r"(bb[nt].x), "r"(bb[nt].y));
                }
            }
        }
        // no trailing barrier: next iteration's sync retires this buffer
    }

    // epilogue: warp w8 -> output row r0+w8, cols xoff + (mt*16+g), valid < 28
    {
        float* orow = outb + (r0 + w8)*HW + xoff;
        #pragma unroll
        for (int nt = 0; nt < 8; nt++) {
            #pragma unroll
            for (int hh = 0; hh < 2; hh++) {
                int n = nt*8 + tq*2 + hh;
                float* op = orow + (size_t)s_sel[n]*NPIX;
                float bi = s_bias[n];
                #pragma unroll
                for (int mt = 0; mt < 2; mt++) {
                    int col = mt*16 + g;
                    if (col < 28) {
                        op[col] = acc[mt][nt][hh] + bi;
                        int col8 = col + 8;
                        if (col8 < 28)
                            op[col8] = acc[mt][nt][2+hh] + bi;
                    }
                }
            }
        }
    }
}

// ---------------------------------------------------------------------------
extern "C" void kernel_launch(void* const* d_in, const int* in_sizes, int n_in,
                              void* d_out, int out_size) {
    const float* x    = (const float*)d_in[0];   // [32,256,56,56]
    const float* w    = (const float*)d_in[1];   // [512,256,3,3]
    const float* bias = (const float*)d_in[2];   // [512]
    const float* rw   = (const float*)d_in[3];   // [512,256]
    const float* rb   = (const float*)d_in[4];   // [512]
    float* out = (float*)d_out;                  // [32,512,56,56]

    cudaFuncSetAttribute(conv_mma, cudaFuncAttributeMaxDynamicSharedMemorySize,
                         SMEMB);

    prep_kernel<<<512 + BB*56, 256>>>(x, w);
    router_kernel<<<BB, OC>>>(rw, rb);
    conv_mma<<<dim3(7, 2, BB), 256, SMEMB>>>(bias, out);
}

// round 17
// speedup vs baseline: 1.0675x; 1.0675x over previous
#include <cuda_runtime.h>
#include <cuda_fp16.h>
#include <cstdint>

#define BB 32
#define IC 256
#define OC 512
#define HW 56
#define NPIX (HW*HW)
#define NF 64

// scratch (no allocations allowed)
__device__ float g_pp[BB*IC*56];                         // pool partials [b][ic][y]
__device__ int   g_sel[BB*NF];
__device__ __align__(16) unsigned short g_xh[(size_t)BB*56*56*IC]; // NHWC fp16, k-permuted
__device__ __align__(16) unsigned short g_wh[OC*9*IC];   // [oc][tap][ic] fp16, k-permuted

__device__ __forceinline__ uint32_t smem_u32(const void* p){
    uint32_t a;
    asm("{ .reg .u64 t; cvta.to.shared.u64 t, %1; cvt.u32.u64 %0, t; }"
        : "=r"(a) : "l"(p));
    return a;
}
#define CPA(dst, src, szr) \
    asm volatile("cp.async.ca.shared.global [%0], [%1], 16, %2;" \
                 :: "r"(dst), "l"(src), "r"(szr))

// ---------------------------------------------------------------------------
// Kernel 1: prep.  Blocks 0..511: weight transpose+fp16 (k-permuted).
// Blocks 512..2303: x NCHW->NHWC fp16 (k-permuted) + pooling partials.
// Permutation within each 16-ic group: half2 slot d2 (0..7) <- src pair
// (d2&1)*4 + (d2>>1): halves [4t..4t+3] hold ics {2t,2t+1,2t+8,2t+9},
// so each mma thread's (k-lo, k-hi) fragment pair is 8B-contiguous.
// ---------------------------------------------------------------------------
__global__ void prep_kernel(const float* __restrict__ x,
                            const float* __restrict__ w) {
    __shared__ float s[128][57];
    const int tid = threadIdx.x, lane = tid & 31, wp = tid >> 5;

    if (blockIdx.x < 512) {                      // ---- weights ----
        int oc = blockIdx.x;
        float* ws = &s[0][0];                    // 2304 floats
        const float4* src = (const float4*)(w + (size_t)oc*2304);
        for (int i = tid; i < 576; i += 256) ((float4*)ws)[i] = src[i];
        __syncthreads();
        for (int j = tid; j < 1152; j += 256) {  // half2 units
            int tap = j >> 7, h2 = j & 127;
            int d2 = h2 & 7;
            int sp = (h2 & ~7) + (d2 & 1)*4 + (d2 >> 1);
            __half2 h = __floats2half2_rn(ws[(2*sp)*9 + tap],
                                          ws[(2*sp+1)*9 + tap]);
            ((__half2*)g_wh)[(size_t)oc*1152 + j] = h;
        }
        return;
    }
    const int bid = blockIdx.x - 512;
    const int b = bid / 56, y = bid - 56*b;
    const float* xp = x + (size_t)b*IC*NPIX + y*HW;

    for (int p = 0; p < 2; p++) {
        #pragma unroll 4
        for (int i = 0; i < 16; i++) {
            int icl = wp*16 + i;
            int ic  = p*128 + icl;
            const float* row = xp + (size_t)ic*NPIX;
            float v0 = row[lane];
            float v1 = (lane < 24) ? row[lane+32] : 0.f;
            s[icl][lane] = v0;
            if (lane < 24) s[icl][lane+32] = v1;
            float sum = v0 + v1;
            #pragma unroll
            for (int o = 16; o; o >>= 1) sum += __shfl_down_sync(~0u, sum, o);
            if (lane == 0) g_pp[((size_t)b*IC + ic)*56 + y] = sum;
        }
        __syncthreads();
        for (int j = tid; j < 3584; j += 256) {
            int xx = j >> 6, icp = j & 63;
            int d2 = icp & 7;
            int lp = (icp & ~7) + (d2 & 1)*4 + (d2 >> 1);
            __half2 h = __floats2half2_rn(s[2*lp][xx], s[2*lp+1][xx]);
            ((__half2*)g_xh)[((size_t)(b*56+y)*56 + xx)*128 + p*64 + icp] = h;
        }
        __syncthreads();
    }
}

// ---------------------------------------------------------------------------
// Kernel 2: router linear + exact top-64 (tie-break by index, = jax top_k).
// ---------------------------------------------------------------------------
__global__ void router_kernel(const float* __restrict__ rw,
                              const float* __restrict__ rb) {
    int b  = blockIdx.x;
    int oc = threadIdx.x;
    __shared__ float ps[IC];
    __shared__ float rs[OC];
    __shared__ int   cnt;
    if (oc < IC) {
        const float* pp = g_pp + ((size_t)b*IC + oc)*56;
        float sum = 0.f;
        #pragma unroll 8
        for (int y = 0; y < 56; y++) sum += pp[y];
        ps[oc] = sum * (1.0f/NPIX);
    }
    if (oc == 0) cnt = 0;
    __syncthreads();
    float s = rb[oc];
    const float* wrow = rw + (size_t)oc * IC;
    #pragma unroll 8
    for (int i = 0; i < IC; i++) s += ps[i] * wrow[i];
    rs[oc] = s;
    __syncthreads();
    int rank = 0;
    for (int j = 0; j < OC; j++) {
        float v = rs[j];
        rank += (v > s) || (v == s && j < oc);
    }
    if (rank < NF) {
        int pos = atomicAdd(&cnt, 1);
        g_sel[b*NF + pos] = oc;
    }
}

// ---------------------------------------------------------------------------
// Kernel 3: fp16 m16n8k16 implicit-GEMM conv, zero-padding tiling.
// CTA = (b, 4-row slab, FULL 56 cols).  Grid (14, 32) = 448 CTAs,
// 7 warps (224 thr), 2 CTAs/SM.  Warp M32 = 4 rows x 8 cols (stripe
// x = 8w..8w+7) -> mma count is the exact minimum (no spatial padding).
// mma row m = 16mt+g -> (y0+2mt, 8w+g); m+8 -> (y0+2mt+1, 8w+g).
// Window smem [y6][x58][ic16] (conflict-free LDS.64), B [oc64][tap9][ic16]
// pitch 144.  16 ic-groups, 2-stage cp.async, div/mod zero-fill (128 slots
// of 224 float4 = exactly the 4x56x512 patch).
// ---------------------------------------------------------------------------
#define WSLOT 16
#define WXN   58
#define WINH  (6*WXN*WSLOT)      // 5568 halves
#define BPH   144
#define BH    (64*BPH)           // 9216 halves
#define STGH  (WINH + BH)        // 14784 halves
#define SMEMB (2*STGH*2)         // 59136 bytes
#define NTHR  224

__global__ __launch_bounds__(NTHR, 2)
void conv_mma(const float* __restrict__ bias, float* __restrict__ out)
{
    extern __shared__ unsigned short smh[];
    __shared__ int   s_sel[64];
    __shared__ float s_bias[64];

    const int tid  = threadIdx.x;
    const int w7   = tid >> 5;            // warp id = x-stripe (0..6)
    const int lane = tid & 31;
    const int g    = lane >> 2;
    const int tq   = lane & 3;
    const int r0   = blockIdx.x * 4;      // slab base row
    const int b    = blockIdx.y;

    if (tid < 64) {
        int sc = g_sel[b*NF + tid];
        s_sel[tid]  = sc;
        s_bias[tid] = bias[sc];
    }
    __syncthreads();

    float* outb = out + (size_t)b*OC*NPIX;
    const uint32_t base_s = smem_u32(smh);

    // ---- stage one 16-ic group into buffer sb ----
    #define STAGE(grp_, sb_) do {                                           \
        uint32_t ws_ = base_s + (sb_)*(STGH*2);                             \
        uint32_t bs_ = ws_ + WINH*2;                                        \
        for (int i = tid; i < 696; i += NTHR) {                             \
            int ch = i & 1, t = i >> 1;                                     \
            int xw = t % 58, yy = t / 58;                                   \
            int gy = r0 + yy - 1, gx = xw - 1;                              \
            bool val = ((unsigned)gy < (unsigned)HW) &&                     \
                       ((unsigned)gx < (unsigned)HW);                       \
            const unsigned short* src = val ?                               \
                (g_xh + (((size_t)(b*56+gy)*56+gx)*256 + (grp_)*16 + ch*8)) \
                : g_xh;                                                     \
            CPA(ws_ + (uint32_t)(t*WSLOT + ch*8)*2u, src, val ? 16 : 0);    \
        }                                                                   \
        for (int i = tid; i < 1152; i += NTHR) {                            \
            int row = i / 18, v = i - row*18;                               \
            int tap = v >> 1, ch = v & 1;                                   \
            const unsigned short* src = g_wh +                              \
                (((size_t)s_sel[row]*9 + tap)*256 + (grp_)*16 + ch*8);      \
            CPA(bs_ + (uint32_t)(row*BPH + tap*16 + ch*8)*2u, src, 16);     \
        }                                                                   \
        asm volatile("cp.async.commit_group;" ::: "memory");                \
    } while(0)

    float acc[2][8][4];
    #pragma unroll
    for (int mt = 0; mt < 2; mt++)
        #pragma unroll
        for (int nt = 0; nt < 8; nt++)
            #pragma unroll
            for (int q = 0; q < 4; q++) acc[mt][nt][q] = 0.f;

    STAGE(0, 0);

    for (int grp = 0; grp < 16; grp++) {
        asm volatile("cp.async.wait_group 0;" ::: "memory");
        __syncthreads();
        if (grp + 1 < 16) STAGE(grp + 1, (grp + 1) & 1);

        const unsigned short* win = smh + (grp & 1)*STGH;
        const unsigned short* Bs  = win + WINH;

        #pragma unroll
        for (int tap = 0; tap < 9; tap++) {
            // embedded zero-fill of the 4x56 output patch (all 512 oc)
            {
                int v = (grp*9 + tap)*NTHR + tid;
                if (v < 28672) {
                    int oc  = v / 56;
                    int rem = v - oc*56;
                    int rr  = rem / 14;
                    int c4  = rem - rr*14;
                    *(float4*)(outb + (size_t)oc*NPIX + (r0+rr)*HW + c4*4)
                        = make_float4(0.f,0.f,0.f,0.f);
                }
            }
            const int dy = tap/3 - 1;
            const int dx = tap - 3*(tap/3) - 1;

            uint2 bb[8];
            #pragma unroll
            for (int nt = 0; nt < 8; nt++)
                bb[nt] = *(const uint2*)(Bs + (nt*8 + g)*BPH + tap*16 + tq*4);
            #pragma unroll
            for (int mt = 0; mt < 2; mt++) {
                // rows m=16mt+g -> (yrel 2mt+dy+1, xrel 8w+g+dx+1); m+8 -> yrel+1
                const unsigned short* ap = win +
                    (((2*mt + dy + 1)*WXN) + (8*w7 + g + dx + 1))*WSLOT + tq*4;
                uint2 aLo = *(const uint2*)ap;                 // row m: k lo|hi
                uint2 aHi = *(const uint2*)(ap + WXN*WSLOT);   // row m+8
                #pragma unroll
                for (int nt = 0; nt < 8; nt++) {
                    asm volatile(
                      "mma.sync.aligned.m16n8k16.row.col.f32.f16.f16.f32 "
                      "{%0,%1,%2,%3}, {%4,%5,%6,%7}, {%8,%9}, {%0,%1,%2,%3};"
                      : "+f"(acc[mt][nt][0]), "+f"(acc[mt][nt][1]),
                        "+f"(acc[mt][nt][2]), "+f"(acc[mt][nt][3])
                      : "r"(aLo.x), "r"(aHi.x), "r"(aLo.y), "r"(aHi.y),
                        "r"(bb[nt].x), "r"(bb[nt].y));
                }
            }
        }
        __syncthreads();   // done reading buf grp&1; next STAGE may overwrite
    }

    // epilogue: warp w7 -> rows (r0+2mt, r0+2mt+1), col 8*w7+g (all valid)
    {
        const int xcol = 8*w7 + g;
        #pragma unroll
        for (int nt = 0; nt < 8; nt++) {
            #pragma unroll
            for (int hh = 0; hh < 2; hh++) {
                int n = nt*8 + tq*2 + hh;
                float* op = outb + (size_t)s_sel[n]*NPIX + xcol;
                float bi = s_bias[n];
                #pragma unroll
                for (int mt = 0; mt < 2; mt++) {
                    op[(r0 + 2*mt    )*HW] = acc[mt][nt][hh]   + bi;
                    op[(r0 + 2*mt + 1)*HW] = acc[mt][nt][2+hh] + bi;
                }
            }
        }
    }
}

// ---------------------------------------------------------------------------
extern "C" void kernel_launch(void* const* d_in, const int* in_sizes, int n_in,
                              void* d_out, int out_size) {
    const float* x    = (const float*)d_in[0];   // [32,256,56,56]
    const float* w    = (const float*)d_in[1];   // [512,256,3,3]
    const float* bias = (const float*)d_in[2];   // [512]
    const float* rw   = (const float*)d_in[3];   // [512,256]
    const float* rb   = (const float*)d_in[4];   // [512]
    float* out = (float*)d_out;                  // [32,512,56,56]

    cudaFuncSetAttribute(conv_mma, cudaFuncAttributeMaxDynamicSharedMemorySize,
                         SMEMB);

    prep_kernel<<<512 + BB*56, 256>>>(x, w);
    router_kernel<<<BB, OC>>>(rw, rb);
    conv_mma<<<dim3(14, BB), NTHR, SMEMB>>>(bias, out);
}